// round 13
// baseline (speedup 1.0000x reference)
#include <cuda_runtime.h>
#include <cstdint>

#define N_DIM   256
#define BS      256
#define TMAX    1000
#define STEP_F  0.01f
#define EPS_F   0.001f

#define CPC     2                 // batch columns per CTA
#define GRID    (BS / CPC)        // 128 CTAs
#define THREADS 256               // 8 warps

// Warp w owns rows [w*32, w*32+32).
// Lane l: rg = l>>4 (row-group 0..1), kl = l&15 (K-slice [kl*16, kl*16+16)).
// Thread rows: w*32 + rg*16 + i, i in [0,16). i<8 -> A in registers, i>=8 -> A in smem.
// 4-level butterfly over the 16 kl-lanes; lane l ends owning row w*32 + l (both cols).

#define SA_F4      8192           // 128 KB of A in smem
#define SX_FLOATS  (2 * 2 * 256)  // double-buffered x, 2 columns, slot-permuted
#define SMEM_BYTES (SA_F4 * 16 + SX_FLOATS * 4)

union F4 { float4 v; float2 h[2]; };

__device__ __forceinline__ void fma2(float2& d, const float2& a, const float2& b) {
    asm("fma.rn.f32x2 %0, %1, %2, %0;"
        : "+l"(reinterpret_cast<unsigned long long&>(d))
        : "l"(reinterpret_cast<const unsigned long long&>(a)),
          "l"(reinterpret_cast<const unsigned long long&>(b)));
}

// float4-slot permutation: logical f4 index f = k>>2 = kl*4 + j  ->  slot = j*16 + kl
// so that for fixed j the 16 kl-lanes read a contiguous 256B block.
__device__ __forceinline__ int slotf(int f) {
    return ((f & 3) << 4) | (f >> 2);
}
// word address (floats) of element k inside one column image
__device__ __forceinline__ int xaddr(int k) {
    return slotf(k >> 2) * 4 + (k & 3);
}

__device__ __forceinline__ float a_elem(const float* __restrict__ W, int r, int k) {
    if (k > r) return  __ldg(&W[r * N_DIM + k]);
    if (k < r) return -__ldg(&W[k * N_DIM + r]);
    return -EPS_F;
}

// Accurate fast tanh: tanh(|y|) = 1 - 2/(exp(2|y|)+1)  (abs err ~1e-7)
__device__ __forceinline__ float fast_tanh(float y) {
    float ay = fabsf(y);
    float e;
    asm("ex2.approx.f32 %0, %1;" : "=f"(e) : "f"(ay * 2.8853900817779268f)); // 2*log2(e)
    float r;
    asm("rcp.approx.f32 %0, %1;" : "=f"(r) : "f"(e + 1.0f));
    float t = fmaf(-2.0f, r, 1.0f);
    return copysignf(t, y);
}

// 4-level butterfly reduce-scatter over 16 kl-lanes.
// v[32] = 16 (row, col) pairs: v[2p]=col0, v[2p+1]=col1 for row-offset p.
// Afterwards lane kl owns pair p=kl -> (y0, y1).
__device__ __forceinline__ void reduce16pair(float* v, int kl, float& y0, float& y1) {
    {   bool hi = (kl & 8) != 0;
        #pragma unroll
        for (int p = 0; p < 8; p++) {
            float s0 = hi ? v[2*p]   : v[2*(p+8)];
            float s1 = hi ? v[2*p+1] : v[2*(p+8)+1];
            float r0 = __shfl_xor_sync(0xffffffffu, s0, 8);
            float r1 = __shfl_xor_sync(0xffffffffu, s1, 8);
            v[2*p]   = (hi ? v[2*(p+8)]   : v[2*p])   + r0;
            v[2*p+1] = (hi ? v[2*(p+8)+1] : v[2*p+1]) + r1;
        }
    }
    {   bool hi = (kl & 4) != 0;
        #pragma unroll
        for (int p = 0; p < 4; p++) {
            float s0 = hi ? v[2*p]   : v[2*(p+4)];
            float s1 = hi ? v[2*p+1] : v[2*(p+4)+1];
            float r0 = __shfl_xor_sync(0xffffffffu, s0, 4);
            float r1 = __shfl_xor_sync(0xffffffffu, s1, 4);
            v[2*p]   = (hi ? v[2*(p+4)]   : v[2*p])   + r0;
            v[2*p+1] = (hi ? v[2*(p+4)+1] : v[2*p+1]) + r1;
        }
    }
    {   bool hi = (kl & 2) != 0;
        #pragma unroll
        for (int p = 0; p < 2; p++) {
            float s0 = hi ? v[2*p]   : v[2*(p+2)];
            float s1 = hi ? v[2*p+1] : v[2*(p+2)+1];
            float r0 = __shfl_xor_sync(0xffffffffu, s0, 2);
            float r1 = __shfl_xor_sync(0xffffffffu, s1, 2);
            v[2*p]   = (hi ? v[2*(p+2)]   : v[2*p])   + r0;
            v[2*p+1] = (hi ? v[2*(p+2)+1] : v[2*p+1]) + r1;
        }
    }
    {   bool hi = (kl & 1) != 0;
        float s0 = hi ? v[0] : v[2];
        float s1 = hi ? v[1] : v[3];
        float r0 = __shfl_xor_sync(0xffffffffu, s0, 1);
        float r1 = __shfl_xor_sync(0xffffffffu, s1, 1);
        y0 = (hi ? v[2] : v[0]) + r0;
        y1 = (hi ? v[3] : v[1]) + r1;
    }
}

extern "C" __global__ void __launch_bounds__(THREADS, 1)
antisym_rnn_kernel(const float* __restrict__ X0,
                   const float* __restrict__ W,
                   const float* __restrict__ by,
                   float* __restrict__ out)
{
    extern __shared__ float smem[];
    float4* sA = reinterpret_cast<float4*>(smem);           // [8192] f4
    float*  sX = smem + SA_F4 * 4;                          // [2][2][256] slot-permuted

    const int tid = threadIdx.x;
    const int w   = tid >> 5;          // warp 0..7
    const int l   = tid & 31;          // lane
    const int rg  = l >> 4;            // row-group 0..1
    const int kl  = l & 15;            // K-lane 0..15
    const int col0 = blockIdx.x * CPC;
    const int row_base = w * 32 + rg * 16;   // this thread's 16 rows start here
    const int k_base   = kl * 16;            // this thread's 16-wide K slice
    const int my_row   = w * 32 + l;         // row this lane owns after reduction

    // ---- one-time init: A ----
    float4 areg[8][4];                  // rows i=0..7, chunks j=0..3
    #pragma unroll
    for (int i = 0; i < 8; i++) {
        int r = row_base + i;
        #pragma unroll
        for (int j = 0; j < 4; j++) {
            int k = k_base + j * 4;
            areg[i][j] = make_float4(a_elem(W, r, k),     a_elem(W, r, k + 1),
                                     a_elem(W, r, k + 2), a_elem(W, r, k + 3));
        }
    }
    #pragma unroll
    for (int i8 = 0; i8 < 8; i8++) {
        int r = row_base + 8 + i8;
        #pragma unroll
        for (int j = 0; j < 4; j++) {
            int k = k_base + j * 4;
            sA[((i8 * 4 + j) * 8 + w) * 32 + l] =
                make_float4(a_elem(W, r, k),     a_elem(W, r, k + 1),
                            a_elem(W, r, k + 2), a_elem(W, r, k + 3));
        }
    }
    const float byv = by[my_row];

    // x0 into slot-permuted smem + t=0 output; own-row values in registers
    #pragma unroll
    for (int c = 0; c < CPC; c++) {
        float v = X0[(col0 + c) * N_DIM + tid];
        sX[(0 * 2 + c) * 256 + xaddr(tid)] = v;
        out[(size_t)(col0 + c) * (TMAX * N_DIM) + tid] = v;
    }
    float xr0 = X0[(col0 + 0) * N_DIM + my_row];
    float xr1 = X0[(col0 + 1) * N_DIM + my_row];
    __syncthreads();

    int buf = 0;
    for (int t = 1; t < TMAX; ++t) {
        const float4* x0p = reinterpret_cast<const float4*>(sX + (buf * 2 + 0) * 256);
        const float4* x1p = reinterpret_cast<const float4*>(sX + (buf * 2 + 1) * 256);

        // lagged output stores of step t-1 (overlap with this step's matvec)
        if (t > 1) {
            size_t tb = (size_t)(t - 1) * N_DIM + my_row;
            out[(size_t)(col0 + 0) * (TMAX * N_DIM) + tb] = xr0;
            out[(size_t)(col0 + 1) * (TMAX * N_DIM) + tb] = xr1;
        }

        float2 acc[16][2];
        #pragma unroll
        for (int i = 0; i < 16; i++) { acc[i][0] = make_float2(0.f, 0.f);
                                       acc[i][1] = make_float2(0.f, 0.f); }

        #pragma unroll
        for (int j = 0; j < 4; j++) {
            F4 xa; xa.v = x0p[j * 16 + kl];
            F4 xb; xb.v = x1p[j * 16 + kl];
            #pragma unroll
            for (int i = 0; i < 8; i++) {
                F4 a; a.v = areg[i][j];
                fma2(acc[i][0], a.h[0], xa.h[0]); fma2(acc[i][0], a.h[1], xa.h[1]);
                fma2(acc[i][1], a.h[0], xb.h[0]); fma2(acc[i][1], a.h[1], xb.h[1]);
            }
            #pragma unroll
            for (int i8 = 0; i8 < 8; i8++) {
                F4 a; a.v = sA[((i8 * 4 + j) * 8 + w) * 32 + l];
                fma2(acc[8 + i8][0], a.h[0], xa.h[0]); fma2(acc[8 + i8][0], a.h[1], xa.h[1]);
                fma2(acc[8 + i8][1], a.h[0], xb.h[0]); fma2(acc[8 + i8][1], a.h[1], xb.h[1]);
            }
        }

        // collapse to scalars: v[2p+c] for row-offset p
        float v[32];
        #pragma unroll
        for (int i = 0; i < 16; i++) {
            v[2*i + 0] = acc[i][0].x + acc[i][0].y;
            v[2*i + 1] = acc[i][1].x + acc[i][1].y;
        }

        float y0, y1;
        reduce16pair(v, kl, y0, y1);
        y0 += byv;
        y1 += byv;

        float xn0 = xr0 + STEP_F * fast_tanh(y0);
        float xn1 = xr1 + STEP_F * fast_tanh(y1);
        xr0 = xn0; xr1 = xn1;

        const int nbuf = buf ^ 1;
        const int pr = xaddr(my_row);
        sX[(nbuf * 2 + 0) * 256 + pr] = xn0;
        sX[(nbuf * 2 + 1) * 256 + pr] = xn1;

        __syncthreads();
        buf = nbuf;
    }

    // final timestep store (STGs lag one step inside the loop)
    {
        size_t tb = (size_t)(TMAX - 1) * N_DIM + my_row;
        out[(size_t)(col0 + 0) * (TMAX * N_DIM) + tb] = xr0;
        out[(size_t)(col0 + 1) * (TMAX * N_DIM) + tb] = xr1;
    }
}

extern "C" void kernel_launch(void* const* d_in, const int* in_sizes, int n_in,
                              void* d_out, int out_size) {
    const float* X0 = (const float*)d_in[0];
    const float* W  = (const float*)d_in[1];
    const float* by = (const float*)d_in[2];
    float* out = (float*)d_out;

    cudaFuncSetAttribute(antisym_rnn_kernel,
                         cudaFuncAttributeMaxDynamicSharedMemorySize, SMEM_BYTES);
    antisym_rnn_kernel<<<GRID, THREADS, SMEM_BYTES>>>(X0, W, by, out);
}

// round 17
// speedup vs baseline: 1.9035x; 1.9035x over previous
#include <cuda_runtime.h>
#include <cstdint>

#define N_DIM   256
#define BS      256
#define TMAX    1000
#define STEP_F  0.01f
#define EPS_F   0.001f

#define CPC     2                 // batch columns per CTA
#define GRID    (BS / CPC)        // 128 CTAs
#define THREADS 256               // 8 warps

// Per-warp layout (R3-proven): warp w owns rows [w*32, w*32+32).
// Lane l: rg = l>>3 (row-group 0..3), kl = l&7 (K-slice [kl*32, kl*32+32)).
// Thread rows: w*32 + rg*8 + i, i in [0,8). i<5 -> A in registers, i>=5 -> A in smem.
// After the 8-lane butterfly reduction lane l owns row w*32 + l.

#define NREG  5                   // A rows per thread in registers
#define NSM   3                   // A rows per thread in smem
#define SA_F4      (256 * NSM * 8)         // 6144 f4 = 96 KB of A in smem
#define SX_FLOATS  (2 * 2 * 256)           // double-buffered x, 2 columns, permuted
#define SMEM_BYTES (SA_F4 * 16 + SX_FLOATS * 4)

union F4 { float4 v; float2 h[2]; };

__device__ __forceinline__ void fma2(float2& d, const float2& a, const float2& b) {
    asm("fma.rn.f32x2 %0, %1, %2, %0;"
        : "+l"(reinterpret_cast<unsigned long long&>(d))
        : "l"(reinterpret_cast<const unsigned long long&>(a)),
          "l"(reinterpret_cast<const unsigned long long&>(b)));
}

__device__ __forceinline__ int permx(int k) {
    // k = (kl<<5) | (j<<2) | e  ->  (j<<5) | (kl<<2) | e
    return (((k >> 2) & 7) << 5) | ((k >> 5) << 2) | (k & 3);
}

__device__ __forceinline__ float a_elem(const float* __restrict__ W, int r, int k) {
    if (k > r) return  __ldg(&W[r * N_DIM + k]);
    if (k < r) return -__ldg(&W[k * N_DIM + r]);
    return -EPS_F;
}

// Accurate fast tanh: tanh(|y|) = 1 - 2/(exp(2|y|)+1)  (abs err ~1e-7)
__device__ __forceinline__ float fast_tanh(float y) {
    float ay = fabsf(y);
    float e;
    asm("ex2.approx.f32 %0, %1;" : "=f"(e) : "f"(ay * 2.8853900817779268f)); // 2*log2(e)
    float r;
    asm("rcp.approx.f32 %0, %1;" : "=f"(r) : "f"(e + 1.0f));
    float t = fmaf(-2.0f, r, 1.0f);
    return copysignf(t, y);
}

// Butterfly reduce-scatter over 8-lane group: v[8] -> lane kl owns sum of v[kl].
__device__ __forceinline__ float reduce8(float* v, int kl) {
    {   bool hi = (kl & 4) != 0;
        #pragma unroll
        for (int i = 0; i < 4; i++) {
            float send = hi ? v[i] : v[i + 4];
            float recv = __shfl_xor_sync(0xffffffffu, send, 4);
            v[i] = (hi ? v[i + 4] : v[i]) + recv;
        }
    }
    {   bool hi = (kl & 2) != 0;
        #pragma unroll
        for (int i = 0; i < 2; i++) {
            float send = hi ? v[i] : v[i + 2];
            float recv = __shfl_xor_sync(0xffffffffu, send, 2);
            v[i] = (hi ? v[i + 2] : v[i]) + recv;
        }
    }
    {   bool hi = (kl & 1) != 0;
        float send = hi ? v[0] : v[1];
        float recv = __shfl_xor_sync(0xffffffffu, send, 1);
        return (hi ? v[1] : v[0]) + recv;
    }
}

extern "C" __global__ void __launch_bounds__(THREADS, 1)
antisym_rnn_kernel(const float* __restrict__ X0,
                   const float* __restrict__ W,
                   const float* __restrict__ by,
                   float* __restrict__ out)
{
    extern __shared__ float smem[];
    float4* sA = reinterpret_cast<float4*>(smem);           // [SA_F4]
    float*  sX = smem + SA_F4 * 4;                          // [2][2][256] permuted

    const int tid = threadIdx.x;
    const int w   = tid >> 5;          // warp 0..7
    const int l   = tid & 31;          // lane
    const int kl  = l & 7;             // K-lane 0..7
    const int rg  = l >> 3;            // row-group 0..3
    const int col0 = blockIdx.x * CPC;
    const int row_base = w * 32 + rg * 8;   // this thread's 8 rows start here
    const int k_base   = kl * 32;           // this thread's K slice
    const int my_row   = w * 32 + l;        // row this lane owns after reduction

    // ---- one-time init: A ----
    float4 areg[NREG][8];
    #pragma unroll
    for (int i = 0; i < NREG; i++) {
        int r = row_base + i;
        #pragma unroll
        for (int j = 0; j < 8; j++) {
            int k = k_base + j * 4;
            areg[i][j] = make_float4(a_elem(W, r, k),     a_elem(W, r, k + 1),
                                     a_elem(W, r, k + 2), a_elem(W, r, k + 3));
        }
    }
    #pragma unroll
    for (int is = 0; is < NSM; is++) {
        int r = row_base + NREG + is;
        #pragma unroll
        for (int j = 0; j < 8; j++) {
            int k = k_base + j * 4;
            sA[((is * 8 + j) * 8 + w) * 32 + l] =
                make_float4(a_elem(W, r, k),     a_elem(W, r, k + 1),
                            a_elem(W, r, k + 2), a_elem(W, r, k + 3));
        }
    }
    const float byv = by[my_row];

    // x0 into permuted smem + t=0 output; lane's own-row values in registers
    #pragma unroll
    for (int c = 0; c < CPC; c++) {
        float v = X0[(col0 + c) * N_DIM + tid];
        sX[(0 * 2 + c) * 256 + permx(tid)] = v;
        out[(size_t)(col0 + c) * (TMAX * N_DIM) + tid] = v;
    }
    float xr0 = X0[(col0 + 0) * N_DIM + my_row];
    float xr1 = X0[(col0 + 1) * N_DIM + my_row];
    __syncthreads();

    int buf = 0;
    for (int t = 1; t < TMAX; ++t) {
        const float4* x0p = reinterpret_cast<const float4*>(sX + (buf * 2 + 0) * 256);
        const float4* x1p = reinterpret_cast<const float4*>(sX + (buf * 2 + 1) * 256);

        // lagged output stores of step t-1 (overlap with this step's matvec)
        if (t > 1) {
            size_t tb = (size_t)(t - 1) * N_DIM + my_row;
            out[(size_t)(col0 + 0) * (TMAX * N_DIM) + tb] = xr0;
            out[(size_t)(col0 + 1) * (TMAX * N_DIM) + tb] = xr1;
        }

        float2 acc[8][2];
        #pragma unroll
        for (int i = 0; i < 8; i++) { acc[i][0] = make_float2(0.f, 0.f);
                                      acc[i][1] = make_float2(0.f, 0.f); }

        #pragma unroll
        for (int j = 0; j < 8; j++) {
            F4 xa; xa.v = x0p[j * 8 + kl];
            F4 xb; xb.v = x1p[j * 8 + kl];
            #pragma unroll
            for (int i = 0; i < NREG; i++) {
                F4 a; a.v = areg[i][j];
                fma2(acc[i][0], a.h[0], xa.h[0]); fma2(acc[i][0], a.h[1], xa.h[1]);
                fma2(acc[i][1], a.h[0], xb.h[0]); fma2(acc[i][1], a.h[1], xb.h[1]);
            }
            #pragma unroll
            for (int is = 0; is < NSM; is++) {
                F4 a; a.v = sA[((is * 8 + j) * 8 + w) * 32 + l];
                fma2(acc[NREG + is][0], a.h[0], xa.h[0]);
                fma2(acc[NREG + is][0], a.h[1], xa.h[1]);
                fma2(acc[NREG + is][1], a.h[0], xb.h[0]);
                fma2(acc[NREG + is][1], a.h[1], xb.h[1]);
            }
        }

        float v0[8], v1[8];
        #pragma unroll
        for (int i = 0; i < 8; i++) {
            v0[i] = acc[i][0].x + acc[i][0].y;
            v1[i] = acc[i][1].x + acc[i][1].y;
        }

        float y0 = reduce8(v0, kl) + byv;
        float y1 = reduce8(v1, kl) + byv;

        float xn0 = xr0 + STEP_F * fast_tanh(y0);
        float xn1 = xr1 + STEP_F * fast_tanh(y1);
        xr0 = xn0; xr1 = xn1;

        const int nbuf = buf ^ 1;
        const int pr = permx(my_row);
        sX[(nbuf * 2 + 0) * 256 + pr] = xn0;
        sX[(nbuf * 2 + 1) * 256 + pr] = xn1;

        __syncthreads();
        buf = nbuf;
    }

    // final timestep store (STGs lag one step inside the loop)
    {
        size_t tb = (size_t)(TMAX - 1) * N_DIM + my_row;
        out[(size_t)(col0 + 0) * (TMAX * N_DIM) + tb] = xr0;
        out[(size_t)(col0 + 1) * (TMAX * N_DIM) + tb] = xr1;
    }
}

extern "C" void kernel_launch(void* const* d_in, const int* in_sizes, int n_in,
                              void* d_out, int out_size) {
    const float* X0 = (const float*)d_in[0];
    const float* W  = (const float*)d_in[1];
    const float* by = (const float*)d_in[2];
    float* out = (float*)d_out;

    cudaFuncSetAttribute(antisym_rnn_kernel,
                         cudaFuncAttributeMaxDynamicSharedMemorySize, SMEM_BYTES);
    antisym_rnn_kernel<<<GRID, THREADS, SMEM_BYTES>>>(X0, W, by, out);
}